// round 12
// baseline (speedup 1.0000x reference)
#include <cuda_runtime.h>
#include <cuda_bf16.h>

// firing_model: next = -prev + tanh(prev @ x) from prev = 0 -> identically
// zero trajectory (tanh(0) = 0 exactly in fp32; time_fomer never influences
// the returned rows). Output [499800, 69] is all zeros -> pure 138 MB
// zero-fill of d_out. HBM-write bound: ~6.9 TB/s achieved across all
// geometries; total = kernel (~20 us) + ~2.9 us fixed graph-replay overhead.
//
// R12 (last untested path): write-through stores (__stwt, st.global.wt)
// instead of evict-first (.cs). Mechanism probe: .cs still write-allocates
// dead lines in L2 (entire 126 MB L2 churned); .wt streams through LTS to
// the memory point. Same exact-cover geometry as the converged best (R10):
// 2 stores per thread, 16 KB per block, 32-bit indexing.

#define FILL_THREADS 256
#define F4_PER_THREAD 2   // each block covers FILL_THREADS * 2 float4s

__global__ void __launch_bounds__(FILL_THREADS)
firing_model_zero_fill_wt(float4* __restrict__ out, int n4) {
    int base = blockIdx.x * (FILL_THREADS * F4_PER_THREAD) + threadIdx.x;
    const float4 z = make_float4(0.0f, 0.0f, 0.0f, 0.0f);

    int i0 = base;
    int i1 = base + FILL_THREADS;
    if (i0 < n4) __stwt(&out[i0], z);
    if (i1 < n4) __stwt(&out[i1], z);
}

__global__ void firing_model_zero_fill_tail(float* __restrict__ out,
                                            long long start, long long n) {
    long long i = start + (long long)blockIdx.x * blockDim.x + threadIdx.x;
    if (i < n) {
        out[i] = 0.0f;
    }
}

extern "C" void kernel_launch(void* const* d_in, const int* in_sizes, int n_in,
                              void* d_out, int out_size) {
    (void)d_in; (void)in_sizes; (void)n_in;

    float* out = (float*)d_out;
    long long n  = (long long)out_size;   // 34,486,200 floats expected
    long long n4 = n >> 2;                // 8,621,550 float4s (exact for this shape)
    long long tail_start = n4 << 2;

    if (n4 > 0) {
        long long per_block = FILL_THREADS * F4_PER_THREAD;
        long long blocks = (n4 + per_block - 1) / per_block;   // ~16,839
        firing_model_zero_fill_wt<<<(unsigned int)blocks, FILL_THREADS>>>(
            (float4*)out, (int)n4);
    }
    if (tail_start < n) {  // not taken for this shape; defensive
        long long tail = n - tail_start;
        int blocks = (int)((tail + 255) / 256);
        firing_model_zero_fill_tail<<<blocks, 256>>>(out, tail_start, n);
    }
}

// round 13
// speedup vs baseline: 1.0254x; 1.0254x over previous
#include <cuda_runtime.h>
#include <cuda_bf16.h>

// firing_model: next = -prev + tanh(prev @ x) from prev = 0 -> identically
// zero trajectory (tanh(0) = 0 exactly in fp32; time_fomer never influences
// the returned rows). Output [499800, 69] is all zeros -> pure 138 MB
// zero-fill of d_out.
//
// FINAL (R13, reverted to measured optimum R10). Exhaustively measured
// design space: stores/thread 1/2/4/8 flat; 128b vs 256b flat; cache policy
// .cs best (.wt -3%, R12); grid-stride -6% (R2); 32-bit indexing best
// profiled (ALU 3.2%). Floor: 137.9 MB mandatory writes at ~6.9 TB/s
// effective HBM3e write ceiling (path-independent LTS cap -> no TMA
// headroom) = ~20 us kernel, + ~2.9 us fixed graph-replay overhead.
// Run-to-run noise band 22.6-23.3 us.

#define FILL_THREADS 256
#define F4_PER_THREAD 2   // each block covers FILL_THREADS * 2 float4s

__global__ void __launch_bounds__(FILL_THREADS)
firing_model_zero_fill2(float4* __restrict__ out, int n4) {
    int base = blockIdx.x * (FILL_THREADS * F4_PER_THREAD) + threadIdx.x;
    const float4 z = make_float4(0.0f, 0.0f, 0.0f, 0.0f);

    int i0 = base;
    int i1 = base + FILL_THREADS;
    if (i0 < n4) __stcs(&out[i0], z);
    if (i1 < n4) __stcs(&out[i1], z);
}

__global__ void firing_model_zero_fill_tail(float* __restrict__ out,
                                            long long start, long long n) {
    long long i = start + (long long)blockIdx.x * blockDim.x + threadIdx.x;
    if (i < n) {
        out[i] = 0.0f;
    }
}

extern "C" void kernel_launch(void* const* d_in, const int* in_sizes, int n_in,
                              void* d_out, int out_size) {
    (void)d_in; (void)in_sizes; (void)n_in;

    float* out = (float*)d_out;
    long long n  = (long long)out_size;   // 34,486,200 floats expected
    long long n4 = n >> 2;                // 8,621,550 float4s (exact for this shape)
    long long tail_start = n4 << 2;

    if (n4 > 0) {
        long long per_block = FILL_THREADS * F4_PER_THREAD;
        long long blocks = (n4 + per_block - 1) / per_block;   // ~16,839
        firing_model_zero_fill2<<<(unsigned int)blocks, FILL_THREADS>>>(
            (float4*)out, (int)n4);
    }
    if (tail_start < n) {  // not taken for this shape; defensive
        long long tail = n - tail_start;
        int blocks = (int)((tail + 255) / 256);
        firing_model_zero_fill_tail<<<blocks, 256>>>(out, tail_start, n);
    }
}